// round 14
// baseline (speedup 1.0000x reference)
#include <cuda_runtime.h>

#define SEQ    4096
#define BATCH  4
#define NLW    50
#define HALO   26                 // max |m+n| under |m*n|<=25
#define TILE   32
#define SPLIT  8
#define SPOS   (TILE + 2*HALO)    // 84
#define NS     449
#define NPAIR  230                // unordered (m,n) pairs incl. 11 diagonals
#define OUTL   (SEQ - 2*NLW)      // 3996

typedef unsigned long long u64;

// ---------------- packed f32x2 helpers ----------------
__device__ __forceinline__ u64 fma2(u64 a, u64 b, u64 c) {
    u64 d; asm("fma.rn.f32x2 %0, %1, %2, %3;" : "=l"(d) : "l"(a), "l"(b), "l"(c)); return d;
}
__device__ __forceinline__ u64 mul2(u64 a, u64 b) {
    u64 d; asm("mul.rn.f32x2 %0, %1, %2;" : "=l"(d) : "l"(a), "l"(b)); return d;
}
__device__ __forceinline__ u64 sub2(u64 a, u64 b) {
    u64 d; asm("sub.rn.f32x2 %0, %1, %2;" : "=l"(d) : "l"(a), "l"(b)); return d;
}
__device__ __forceinline__ u64 add2(u64 a, u64 b) {
    u64 d; asm("add.rn.f32x2 %0, %1, %2;" : "=l"(d) : "l"(a), "l"(b)); return d;
}
__device__ __forceinline__ u64 packf2(float2 v) {
    u64 d; asm("mov.b64 %0, {%1, %2};" : "=l"(d) : "f"(v.x), "f"(v.y)); return d;
}
__device__ __forceinline__ u64 pack2(float x) {
    u64 d; asm("mov.b64 %0, {%1, %1};" : "=l"(d) : "f"(x)); return d;
}
__device__ __forceinline__ float2 unpackf2(u64 v) {
    float2 f; asm("mov.b64 {%0, %1}, %2;" : "=f"(f.x), "=f"(f.y) : "l"(v)); return f;
}

// ---------------- compile-time pair schedule ----------------
struct PTab {
    int S0f[52]; int NMf[51];
    int NR;
    int RM[24];          // m per run
    int RN0[24];         // starting (highest) n per run
    int RP0[25];         // pair-index prefix per run
    short PS1[NPAIR];    // s-index of (m,n)
    short PS2[NPAIR];    // s-index of (n,m); -1 for diagonal
    int CB[SPLIT + 1];   // per-warp chunk boundaries in pair space
    int CRI[SPLIT];      // run containing each chunk start
    constexpr PTab() : S0f(), NMf(), NR(0), RM(), RN0(), RP0(), PS1(), PS2(), CB(), CRI() {
        int s = 0;
        for (int mi = 0; mi < 51; ++mi) {
            int m = mi - 25, nm = 0;
            for (int n = 1; n <= 25; ++n) { int pp = m * n; if (pp < 0) pp = -pp; if (pp <= 25) nm = n; }
            if (m == 0) nm = 25;
            S0f[mi] = s; NMf[mi] = nm; s += 2 * nm + 1;
        }
        S0f[51] = s;  // 449
        int p = 0, r = 0;
        for (int mg = 0; mg < 11; ++mg) {
            int m = mg - 5, am = m < 0 ? -m : m, K = NMf[m + 25];
            int lo1 = (m >= 0) ? m : (am + 1);
            if (K >= lo1) {
                RM[r] = m; RN0[r] = K; RP0[r] = p;
                for (int n = K; n >= lo1; --n) {
                    PS1[p] = (short)(S0f[m + 25] + (n + NMf[m + 25]));
                    PS2[p] = (short)((n == m) ? -1 : (S0f[n + 25] + (m + NMf[n + 25])));
                    ++p;
                }
                ++r;
            }
            int hi2 = (m > 0) ? -m : ((m == 0) ? -1 : -am);
            if (hi2 >= -K) {
                RM[r] = m; RN0[r] = hi2; RP0[r] = p;
                for (int n = hi2; n >= -K; --n) {
                    PS1[p] = (short)(S0f[m + 25] + (n + NMf[m + 25]));
                    PS2[p] = (short)((n == m) ? -1 : (S0f[n + 25] + (m + NMf[n + 25])));
                    ++p;
                }
                ++r;
            }
        }
        RP0[r] = p; NR = r;   // p == 230, r == 21
        for (int t = 0; t <= SPLIT; ++t) CB[t] = NPAIR * t / SPLIT;
        for (int t = 0; t < SPLIT; ++t) {
            int k = 0;
            while (RP0[k + 1] <= CB[t]) ++k;
            CRI[t] = k;
        }
    }
};
__constant__ PTab c_pt = PTab();

// scratch (Ps-scaled), packed mode-pairs
__device__ u64 g_E1r[BATCH * SEQ];
__device__ u64 g_E1i[BATCH * SEQ];
__device__ u64 g_Mr [BATCH * SEQ];
__device__ u64 g_Mi [BATCH * SEQ];

// ---------------------------------------------------------------------------
// Stage 1:  E1[l] = Ps * sum_{pairs} E[l-m] * ( w1sym * E[l-n]*conj(E[l-m-n]) )
//           M [l] = same with w2sym     (symmetrized weights, 230 iters)
// ---------------------------------------------------------------------------
__global__ void __launch_bounds__(TILE * SPLIT, 4)
stage1_kernel(const float2* __restrict__ Er, const float2* __restrict__ Ei,
              const float*  __restrict__ task,
              const float*  __restrict__ w1r, const float* __restrict__ w1i,
              const float*  __restrict__ w2r, const float* __restrict__ w2i)
{
    __shared__ ulonglong2 sE[SPOS];                  // {re2, im2}
    __shared__ ulonglong2 sWa[NPAIR];                // w1sym {r2, i2}
    __shared__ ulonglong2 sWb[NPAIR];                // w2sym {r2, i2}
    __shared__ ulonglong2 sR1[SPLIT - 1][TILE];
    __shared__ ulonglong2 sR2[SPLIT - 1][TILE];

    const int tile = blockIdx.x, b = blockIdx.y;
    const int tx = threadIdx.x, ty = threadIdx.y;
    const int tid = ty * TILE + tx;
    const int base = tile * TILE;
    const float2* Erb = Er + b * SEQ;
    const float2* Eib = Ei + b * SEQ;

    for (int i = tid; i < SPOS; i += TILE * SPLIT) {
        int pp = (base - HALO + i) & (SEQ - 1);
        sE[i] = make_ulonglong2(packf2(Erb[pp]), packf2(Eib[pp]));
    }
    for (int p0 = tid; p0 < NPAIR; p0 += TILE * SPLIT) {
        const int s1 = c_pt.PS1[p0], s2 = c_pt.PS2[p0];
        float ar = w1r[s1], ai = w1i[s1];
        float br = w2r[s1], bi = w2i[s1];
        if (s2 >= 0) { ar += w1r[s2]; ai += w1i[s2]; br += w2r[s2]; bi += w2i[s2]; }
        sWa[p0] = make_ulonglong2(pack2(ar), pack2(ai));
        sWb[p0] = make_ulonglong2(pack2(br), pack2(bi));
    }
    __syncthreads();

    const int li = tx + HALO;
    const u64 z = 0;
    u64 e1r = 0, e1i = 0, mr = 0, mi_ = 0;

    int p = c_pt.CB[ty];
    const int pEnd = c_pt.CB[ty + 1];
    int r = c_pt.CRI[ty];
    while (p < pEnd) {
        const int m   = c_pt.RM[r];
        const int n0  = c_pt.RN0[r] - (p - c_pt.RP0[r]);
        const int rEnd = min(c_pt.RP0[r + 1], pEnd);
        const ulonglong2 av = sE[li - m];
        int ib = li - n0;          // l - n  (n descending -> ib increments)
        int ic = ib - m;           // l - m - n
        u64 y1r = 0, y1i = 0, y2r = 0, y2i = 0;
        #pragma unroll 2
        for (; p < rEnd; ++p, ++ib, ++ic) {
            const ulonglong2 bv = sE[ib];
            const ulonglong2 cv = sE[ic];
            const ulonglong2 wa = sWa[p];
            const ulonglong2 wb = sWb[p];
            // t = E[l-n] * conj(E[l-m-n])
            const u64 tr  = fma2(bv.y, cv.y, mul2(bv.x, cv.x));
            const u64 ti  = sub2(mul2(bv.y, cv.x), mul2(bv.x, cv.y));
            const u64 nti = sub2(z, ti);
            y1r = fma2(wa.x, tr, y1r);  y1r = fma2(wa.y, nti, y1r);
            y1i = fma2(wa.x, ti, y1i);  y1i = fma2(wa.y, tr,  y1i);
            y2r = fma2(wb.x, tr, y2r);  y2r = fma2(wb.y, nti, y2r);
            y2i = fma2(wb.x, ti, y2i);  y2i = fma2(wb.y, tr,  y2i);
        }
        const u64 nai = sub2(z, av.y);
        e1r = fma2(av.x, y1r, e1r);  e1r = fma2(nai,  y1i, e1r);
        e1i = fma2(av.x, y1i, e1i);  e1i = fma2(av.y, y1r, e1i);
        mr  = fma2(av.x, y2r, mr);   mr  = fma2(nai,  y2i, mr);
        mi_ = fma2(av.x, y2i, mi_);  mi_ = fma2(av.y, y2r, mi_);
        ++r;
    }

    if (ty > 0) {
        sR1[ty - 1][tx] = make_ulonglong2(e1r, e1i);
        sR2[ty - 1][tx] = make_ulonglong2(mr, mi_);
    }
    __syncthreads();
    if (ty == 0) {
        #pragma unroll
        for (int j = 0; j < SPLIT - 1; ++j) {
            const ulonglong2 r1 = sR1[j][tx], r2 = sR2[j][tx];
            e1r = add2(e1r, r1.x);  e1i = add2(e1i, r1.y);
            mr  = add2(mr,  r2.x);  mi_ = add2(mi_, r2.y);
        }
        const u64 Ps = pack2(exp10f(task[b * 4] * 0.1f) * 0.5f);
        const int gi = b * SEQ + base + tx;
        g_E1r[gi] = mul2(e1r, Ps);
        g_E1i[gi] = mul2(e1i, Ps);
        g_Mr [gi] = mul2(mr,  Ps);
        g_Mi [gi] = mul2(mi_, Ps);
    }
}

// ---------------------------------------------------------------------------
// Stage 2 (pairwise): per pair {(m,n),(n,m)} in group m:
//   F += G[l-m] * ( w1a * E[l-n]*conj(E[l-m-n]) )
//      + E[l-m] * ( w1b * G[l-n]*conj(E[l-m-n]) + w2s * E[l-n]*conj(G[l-m-n]) )
//   out = E + 0.1*E1 + 0.01*Ps*F,  sliced l in [50, 4046)
// ---------------------------------------------------------------------------
__global__ void __launch_bounds__(TILE * SPLIT, 4)
stage2_kernel(const float2* __restrict__ Er, const float2* __restrict__ Ei,
              const float*  __restrict__ task,
              const float*  __restrict__ fcr, const float* __restrict__ fci,
              float4* __restrict__ out)
{
    __shared__ ulonglong2 sE[SPOS];
    __shared__ ulonglong2 sM[SPOS];                  // G = E1_mid (Ps-scaled)
    __shared__ ulonglong2 sWa[NPAIR];                // w1a = fc[s1]
    __shared__ ulonglong2 sWb[NPAIR];                // w1b = fc[s2] (0 if diag)
    __shared__ ulonglong2 sWc[NPAIR];                // w2s = fc2[s1] (+ fc2[s2])
    __shared__ ulonglong2 sR[SPLIT - 1][TILE];

    const int tile = blockIdx.x, b = blockIdx.y;
    const int tx = threadIdx.x, ty = threadIdx.y;
    const int tid = ty * TILE + tx;
    const int base = tile * TILE;
    const float2* Erb = Er + b * SEQ;
    const float2* Eib = Ei + b * SEQ;

    for (int i = tid; i < SPOS; i += TILE * SPLIT) {
        int pp = (base - HALO + i) & (SEQ - 1);
        int gp = b * SEQ + pp;
        sE[i] = make_ulonglong2(packf2(Erb[pp]), packf2(Eib[pp]));
        sM[i] = make_ulonglong2(g_Mr[gp], g_Mi[gp]);
    }
    for (int p0 = tid; p0 < NPAIR; p0 += TILE * SPLIT) {
        const int s1 = c_pt.PS1[p0], s2 = c_pt.PS2[p0];
        const float a_r = fcr[s1], a_i = fci[s1];
        float b_r = 0.f, b_i = 0.f;
        float cR = fcr[NS + s1], cI = fci[NS + s1];
        if (s2 >= 0) { b_r = fcr[s2]; b_i = fci[s2]; cR += fcr[NS + s2]; cI += fci[NS + s2]; }
        sWa[p0] = make_ulonglong2(pack2(a_r), pack2(a_i));
        sWb[p0] = make_ulonglong2(pack2(b_r), pack2(b_i));
        sWc[p0] = make_ulonglong2(pack2(cR), pack2(cI));
    }
    __syncthreads();

    const int li = tx + HALO;
    const u64 z = 0;
    u64 fr = 0, fi = 0;

    int p = c_pt.CB[ty];
    const int pEnd = c_pt.CB[ty + 1];
    int r = c_pt.CRI[ty];
    while (p < pEnd) {
        const int m   = c_pt.RM[r];
        const int n0  = c_pt.RN0[r] - (p - c_pt.RP0[r]);
        const int rEnd = min(c_pt.RP0[r + 1], pEnd);
        const int lia = li - m;
        const ulonglong2 av = sE[lia];    // E[l-m]
        const ulonglong2 gv = sM[lia];    // G[l-m]
        int ib = li - n0;
        int ic = ib - m;
        u64 y1r = 0, y1i = 0, yar = 0, yai = 0;
        #pragma unroll 2
        for (; p < rEnd; ++p, ++ib, ++ic) {
            // batched loads first (front-loaded MLP)
            const ulonglong2 bv = sE[ib];  // E[l-n]
            const ulonglong2 gn = sM[ib];  // G[l-n]
            const ulonglong2 cv = sE[ic];  // E[l-m-n]
            const ulonglong2 dv = sM[ic];  // G[l-m-n]
            const ulonglong2 wa = sWa[p];
            const ulonglong2 wb = sWb[p];
            const ulonglong2 wc = sWc[p];
            // p1 = E[l-n]*conj(E[l-m-n])
            const u64 p1r = fma2(bv.y, cv.y, mul2(bv.x, cv.x));
            const u64 p1i = sub2(mul2(bv.y, cv.x), mul2(bv.x, cv.y));
            // rr = G[l-n]*conj(E[l-m-n])
            const u64 rrr = fma2(gn.y, cv.y, mul2(gn.x, cv.x));
            const u64 rri = sub2(mul2(gn.y, cv.x), mul2(gn.x, cv.y));
            // qq = E[l-n]*conj(G[l-m-n])
            const u64 qqr = fma2(bv.y, dv.y, mul2(bv.x, dv.x));
            const u64 qqi = sub2(mul2(bv.y, dv.x), mul2(bv.x, dv.y));
            const u64 np1 = sub2(z, p1i);
            const u64 nrr = sub2(z, rri);
            const u64 nqq = sub2(z, qqi);
            y1r = fma2(wa.x, p1r, y1r);  y1r = fma2(wa.y, np1, y1r);
            y1i = fma2(wa.x, p1i, y1i);  y1i = fma2(wa.y, p1r, y1i);
            yar = fma2(wb.x, rrr, yar);  yar = fma2(wb.y, nrr, yar);
            yai = fma2(wb.x, rri, yai);  yai = fma2(wb.y, rrr, yai);
            yar = fma2(wc.x, qqr, yar);  yar = fma2(wc.y, nqq, yar);
            yai = fma2(wc.x, qqi, yai);  yai = fma2(wc.y, qqr, yai);
        }
        // F += G[l-m]*y1 + E[l-m]*ya
        const u64 ngv = sub2(z, gv.y);
        const u64 nav = sub2(z, av.y);
        fr = fma2(gv.x, y1r, fr);  fr = fma2(ngv, y1i, fr);
        fi = fma2(gv.x, y1i, fi);  fi = fma2(gv.y, y1r, fi);
        fr = fma2(av.x, yar, fr);  fr = fma2(nav, yai, fr);
        fi = fma2(av.x, yai, fi);  fi = fma2(av.y, yar, fi);
        ++r;
    }

    if (ty > 0)
        sR[ty - 1][tx] = make_ulonglong2(fr, fi);
    __syncthreads();
    if (ty == 0) {
        #pragma unroll
        for (int j = 0; j < SPLIT - 1; ++j) {
            const ulonglong2 rr = sR[j][tx];
            fr = add2(fr, rr.x);  fi = add2(fi, rr.y);
        }
        const int l = base + tx;
        if (l >= NLW && l < SEQ - NLW) {
            const float Psf = exp10f(task[b * 4] * 0.1f) * 0.5f;
            const u64 g2 = pack2(0.01f * Psf);
            const u64 c01 = pack2(0.1f);
            const int gi = b * SEQ + l;
            const ulonglong2 ev = sE[li];
            u64 outr = fma2(g2, fr, fma2(c01, g_E1r[gi], ev.x));
            u64 outi = fma2(g2, fi, fma2(c01, g_E1i[gi], ev.y));
            const float2 orr = unpackf2(outr);
            const float2 oii = unpackf2(outi);
            out[b * OUTL + (l - NLW)] = make_float4(orr.x, oii.x, orr.y, oii.y);
        }
    }
}

extern "C" void kernel_launch(void* const* d_in, const int* in_sizes, int n_in,
                              void* d_out, int out_size)
{
    const float2* Er   = (const float2*)d_in[0];
    const float2* Ei   = (const float2*)d_in[1];
    const float*  task = (const float*)d_in[2];
    const float*  w1r  = (const float*)d_in[3];
    const float*  w1i  = (const float*)d_in[4];
    const float*  w2r  = (const float*)d_in[5];
    const float*  w2i  = (const float*)d_in[6];
    const float*  fcr  = (const float*)d_in[7];
    const float*  fci  = (const float*)d_in[8];

    dim3 grid(SEQ / TILE, BATCH);
    dim3 blk(TILE, SPLIT);
    stage1_kernel<<<grid, blk>>>(Er, Ei, task, w1r, w1i, w2r, w2i);
    stage2_kernel<<<grid, blk>>>(Er, Ei, task, fcr, fci, (float4*)d_out);
}

// round 17
// speedup vs baseline: 1.1202x; 1.1202x over previous
#include <cuda_runtime.h>

#define SEQ    4096
#define BATCH  4
#define NLW    50
#define HALO   26                 // max |m+n| under |m*n|<=25
#define TILE   32
#define SPLIT  8
#define SPOS   (TILE + 2*HALO)    // 84
#define NS     449
#define NPAIR  230                // unordered (m,n) pairs incl. 11 diagonals
#define OUTL   (SEQ - 2*NLW)      // 3996

typedef unsigned long long u64;

// ---------------- packed f32x2 helpers ----------------
__device__ __forceinline__ u64 fma2(u64 a, u64 b, u64 c) {
    u64 d; asm("fma.rn.f32x2 %0, %1, %2, %3;" : "=l"(d) : "l"(a), "l"(b), "l"(c)); return d;
}
__device__ __forceinline__ u64 mul2(u64 a, u64 b) {
    u64 d; asm("mul.rn.f32x2 %0, %1, %2;" : "=l"(d) : "l"(a), "l"(b)); return d;
}
__device__ __forceinline__ u64 sub2(u64 a, u64 b) {
    u64 d; asm("sub.rn.f32x2 %0, %1, %2;" : "=l"(d) : "l"(a), "l"(b)); return d;
}
__device__ __forceinline__ u64 add2(u64 a, u64 b) {
    u64 d; asm("add.rn.f32x2 %0, %1, %2;" : "=l"(d) : "l"(a), "l"(b)); return d;
}
__device__ __forceinline__ u64 packf2(float2 v) {
    u64 d; asm("mov.b64 %0, {%1, %2};" : "=l"(d) : "f"(v.x), "f"(v.y)); return d;
}
__device__ __forceinline__ u64 pack2(float x) {
    u64 d; asm("mov.b64 %0, {%1, %1};" : "=l"(d) : "f"(x)); return d;
}
__device__ __forceinline__ float2 unpackf2(u64 v) {
    float2 f; asm("mov.b64 {%0, %1}, %2;" : "=f"(f.x), "=f"(f.y) : "l"(v)); return f;
}

// ---------------- compile-time pair schedule ----------------
struct PTab {
    int S0f[52]; int NMf[51];
    int NR;
    int RM[24];          // m per run
    int RN0[24];         // starting (highest) n per run
    int RP0[25];         // pair-index prefix per run
    short PS1[NPAIR];    // s-index of (m,n)
    short PS2[NPAIR];    // s-index of (n,m); -1 for diagonal
    int CB[SPLIT + 1];   // per-warp chunk boundaries in pair space
    int CRI[SPLIT];      // run containing each chunk start
    constexpr PTab() : S0f(), NMf(), NR(0), RM(), RN0(), RP0(), PS1(), PS2(), CB(), CRI() {
        int s = 0;
        for (int mi = 0; mi < 51; ++mi) {
            int m = mi - 25, nm = 0;
            for (int n = 1; n <= 25; ++n) { int pp = m * n; if (pp < 0) pp = -pp; if (pp <= 25) nm = n; }
            if (m == 0) nm = 25;
            S0f[mi] = s; NMf[mi] = nm; s += 2 * nm + 1;
        }
        S0f[51] = s;  // 449
        int p = 0, r = 0;
        for (int mg = 0; mg < 11; ++mg) {
            int m = mg - 5, am = m < 0 ? -m : m, K = NMf[m + 25];
            int lo1 = (m >= 0) ? m : (am + 1);
            if (K >= lo1) {
                RM[r] = m; RN0[r] = K; RP0[r] = p;
                for (int n = K; n >= lo1; --n) {
                    PS1[p] = (short)(S0f[m + 25] + (n + NMf[m + 25]));
                    PS2[p] = (short)((n == m) ? -1 : (S0f[n + 25] + (m + NMf[n + 25])));
                    ++p;
                }
                ++r;
            }
            int hi2 = (m > 0) ? -m : ((m == 0) ? -1 : -am);
            if (hi2 >= -K) {
                RM[r] = m; RN0[r] = hi2; RP0[r] = p;
                for (int n = hi2; n >= -K; --n) {
                    PS1[p] = (short)(S0f[m + 25] + (n + NMf[m + 25]));
                    PS2[p] = (short)((n == m) ? -1 : (S0f[n + 25] + (m + NMf[n + 25])));
                    ++p;
                }
                ++r;
            }
        }
        RP0[r] = p; NR = r;   // p == 230, r == 21
        for (int t = 0; t <= SPLIT; ++t) CB[t] = NPAIR * t / SPLIT;
        for (int t = 0; t < SPLIT; ++t) {
            int k = 0;
            while (RP0[k + 1] <= CB[t]) ++k;
            CRI[t] = k;
        }
    }
};
__constant__ PTab c_pt = PTab();

// scratch (Ps-scaled), packed mode-pairs
__device__ u64 g_E1r[BATCH * SEQ];
__device__ u64 g_E1i[BATCH * SEQ];
__device__ u64 g_Mr [BATCH * SEQ];
__device__ u64 g_Mi [BATCH * SEQ];

// ---------------------------------------------------------------------------
// Stage 1:  E1[l] = Ps * sum_{pairs} E[l-m] * ( w1sym * E[l-n]*conj(E[l-m-n]) )
//           M [l] = same with w2sym     (symmetrized weights, 230 iters)
// Weights stored UNduplicated (float4, one LDS.128/iter); duplicated via mov.
// ---------------------------------------------------------------------------
__global__ void __launch_bounds__(TILE * SPLIT, 4)
stage1_kernel(const float2* __restrict__ Er, const float2* __restrict__ Ei,
              const float*  __restrict__ task,
              const float*  __restrict__ w1r, const float* __restrict__ w1i,
              const float*  __restrict__ w2r, const float* __restrict__ w2i)
{
    __shared__ ulonglong2 sE[SPOS];                  // {re2, im2}
    __shared__ float4 sW[NPAIR];                     // {w1r,w1i,w2r,w2i} sym
    __shared__ ulonglong2 sR1[SPLIT - 1][TILE];
    __shared__ ulonglong2 sR2[SPLIT - 1][TILE];

    const int tile = blockIdx.x, b = blockIdx.y;
    const int tx = threadIdx.x, ty = threadIdx.y;
    const int tid = ty * TILE + tx;
    const int base = tile * TILE;
    const float2* Erb = Er + b * SEQ;
    const float2* Eib = Ei + b * SEQ;

    for (int i = tid; i < SPOS; i += TILE * SPLIT) {
        int pp = (base - HALO + i) & (SEQ - 1);
        sE[i] = make_ulonglong2(packf2(Erb[pp]), packf2(Eib[pp]));
    }
    for (int p0 = tid; p0 < NPAIR; p0 += TILE * SPLIT) {
        const int s1 = c_pt.PS1[p0], s2 = c_pt.PS2[p0];
        float ar = w1r[s1], ai = w1i[s1];
        float br = w2r[s1], bi = w2i[s1];
        if (s2 >= 0) { ar += w1r[s2]; ai += w1i[s2]; br += w2r[s2]; bi += w2i[s2]; }
        sW[p0] = make_float4(ar, ai, br, bi);
    }
    __syncthreads();

    const int li = tx + HALO;
    const u64 z = 0;
    u64 e1r = 0, e1i = 0, mr = 0, mi_ = 0;

    int p = c_pt.CB[ty];
    const int pEnd = c_pt.CB[ty + 1];
    int r = c_pt.CRI[ty];
    while (p < pEnd) {
        const int m   = c_pt.RM[r];
        const int n0  = c_pt.RN0[r] - (p - c_pt.RP0[r]);
        const int rEnd = min(c_pt.RP0[r + 1], pEnd);
        const ulonglong2 av = sE[li - m];
        int ib = li - n0;          // l - n  (n descending -> ib increments)
        int ic = ib - m;           // l - m - n
        u64 y1r = 0, y1i = 0, y2r = 0, y2i = 0;
        #pragma unroll 2
        for (; p < rEnd; ++p, ++ib, ++ic) {
            const ulonglong2 bv = sE[ib];
            const ulonglong2 cv = sE[ic];
            const float4 wf = sW[p];                 // one LDS.128
            const u64 wax = pack2(wf.x), way = pack2(wf.y);
            const u64 wbx = pack2(wf.z), wby = pack2(wf.w);
            // t = E[l-n] * conj(E[l-m-n])
            const u64 tr  = fma2(bv.y, cv.y, mul2(bv.x, cv.x));
            const u64 ti  = sub2(mul2(bv.y, cv.x), mul2(bv.x, cv.y));
            const u64 nti = sub2(z, ti);
            y1r = fma2(wax, tr, y1r);  y1r = fma2(way, nti, y1r);
            y1i = fma2(wax, ti, y1i);  y1i = fma2(way, tr,  y1i);
            y2r = fma2(wbx, tr, y2r);  y2r = fma2(wby, nti, y2r);
            y2i = fma2(wbx, ti, y2i);  y2i = fma2(wby, tr,  y2i);
        }
        const u64 nai = sub2(z, av.y);
        e1r = fma2(av.x, y1r, e1r);  e1r = fma2(nai,  y1i, e1r);
        e1i = fma2(av.x, y1i, e1i);  e1i = fma2(av.y, y1r, e1i);
        mr  = fma2(av.x, y2r, mr);   mr  = fma2(nai,  y2i, mr);
        mi_ = fma2(av.x, y2i, mi_);  mi_ = fma2(av.y, y2r, mi_);
        ++r;
    }

    if (ty > 0) {
        sR1[ty - 1][tx] = make_ulonglong2(e1r, e1i);
        sR2[ty - 1][tx] = make_ulonglong2(mr, mi_);
    }
    __syncthreads();
    if (ty == 0) {
        #pragma unroll
        for (int j = 0; j < SPLIT - 1; ++j) {
            const ulonglong2 r1 = sR1[j][tx], r2 = sR2[j][tx];
            e1r = add2(e1r, r1.x);  e1i = add2(e1i, r1.y);
            mr  = add2(mr,  r2.x);  mi_ = add2(mi_, r2.y);
        }
        const u64 Ps = pack2(exp10f(task[b * 4] * 0.1f) * 0.5f);
        const int gi = b * SEQ + base + tx;
        g_E1r[gi] = mul2(e1r, Ps);
        g_E1i[gi] = mul2(e1i, Ps);
        g_Mr [gi] = mul2(mr,  Ps);
        g_Mi [gi] = mul2(mi_, Ps);
    }
}

// ---------------------------------------------------------------------------
// Stage 2 (pairwise): per pair {(m,n),(n,m)} in group m:
//   F += G[l-m] * ( w1a * E[l-n]*conj(E[l-m-n]) )
//      + E[l-m] * ( w1b * G[l-n]*conj(E[l-m-n]) + w2s * E[l-n]*conj(G[l-m-n]) )
//   out = E + 0.1*E1 + 0.01*Ps*F,  sliced l in [50, 4046)
// Weights UNduplicated: float4 (wa,wb) + float2 (wc) = 2 LDS/iter (was 3).
// ---------------------------------------------------------------------------
__global__ void __launch_bounds__(TILE * SPLIT, 4)
stage2_kernel(const float2* __restrict__ Er, const float2* __restrict__ Ei,
              const float*  __restrict__ task,
              const float*  __restrict__ fcr, const float* __restrict__ fci,
              float4* __restrict__ out)
{
    __shared__ ulonglong2 sE[SPOS];
    __shared__ ulonglong2 sM[SPOS];                  // G = E1_mid (Ps-scaled)
    __shared__ float4 sWq[NPAIR];                    // {a_r, a_i, b_r, b_i}
    __shared__ float2 sWc[NPAIR];                    // {cR, cI}
    __shared__ ulonglong2 sR[SPLIT - 1][TILE];

    const int tile = blockIdx.x, b = blockIdx.y;
    const int tx = threadIdx.x, ty = threadIdx.y;
    const int tid = ty * TILE + tx;
    const int base = tile * TILE;
    const float2* Erb = Er + b * SEQ;
    const float2* Eib = Ei + b * SEQ;

    for (int i = tid; i < SPOS; i += TILE * SPLIT) {
        int pp = (base - HALO + i) & (SEQ - 1);
        int gp = b * SEQ + pp;
        sE[i] = make_ulonglong2(packf2(Erb[pp]), packf2(Eib[pp]));
        sM[i] = make_ulonglong2(g_Mr[gp], g_Mi[gp]);
    }
    for (int p0 = tid; p0 < NPAIR; p0 += TILE * SPLIT) {
        const int s1 = c_pt.PS1[p0], s2 = c_pt.PS2[p0];
        const float a_r = fcr[s1], a_i = fci[s1];
        float b_r = 0.f, b_i = 0.f;
        float cR = fcr[NS + s1], cI = fci[NS + s1];
        if (s2 >= 0) { b_r = fcr[s2]; b_i = fci[s2]; cR += fcr[NS + s2]; cI += fci[NS + s2]; }
        sWq[p0] = make_float4(a_r, a_i, b_r, b_i);
        sWc[p0] = make_float2(cR, cI);
    }
    __syncthreads();

    const int li = tx + HALO;
    const u64 z = 0;
    u64 fr = 0, fi = 0;

    int p = c_pt.CB[ty];
    const int pEnd = c_pt.CB[ty + 1];
    int r = c_pt.CRI[ty];
    while (p < pEnd) {
        const int m   = c_pt.RM[r];
        const int n0  = c_pt.RN0[r] - (p - c_pt.RP0[r]);
        const int rEnd = min(c_pt.RP0[r + 1], pEnd);
        const int lia = li - m;
        const ulonglong2 av = sE[lia];    // E[l-m]
        const ulonglong2 gv = sM[lia];    // G[l-m]
        int ib = li - n0;
        int ic = ib - m;
        u64 y1r = 0, y1i = 0, yar = 0, yai = 0;
        #pragma unroll 2
        for (; p < rEnd; ++p, ++ib, ++ic) {
            // batched loads first (front-loaded MLP): 4 data + 2 weight LDS
            const ulonglong2 bv = sE[ib];  // E[l-n]
            const ulonglong2 gn = sM[ib];  // G[l-n]
            const ulonglong2 cv = sE[ic];  // E[l-m-n]
            const ulonglong2 dv = sM[ic];  // G[l-m-n]
            const float4 wq = sWq[p];
            const float2 wc2 = sWc[p];
            const u64 wax = pack2(wq.x), way = pack2(wq.y);
            const u64 wbx = pack2(wq.z), wby = pack2(wq.w);
            const u64 wcx = pack2(wc2.x), wcy = pack2(wc2.y);
            // p1 = E[l-n]*conj(E[l-m-n])
            const u64 p1r = fma2(bv.y, cv.y, mul2(bv.x, cv.x));
            const u64 p1i = sub2(mul2(bv.y, cv.x), mul2(bv.x, cv.y));
            // rr = G[l-n]*conj(E[l-m-n])
            const u64 rrr = fma2(gn.y, cv.y, mul2(gn.x, cv.x));
            const u64 rri = sub2(mul2(gn.y, cv.x), mul2(gn.x, cv.y));
            // qq = E[l-n]*conj(G[l-m-n])
            const u64 qqr = fma2(bv.y, dv.y, mul2(bv.x, dv.x));
            const u64 qqi = sub2(mul2(bv.y, dv.x), mul2(bv.x, dv.y));
            const u64 np1 = sub2(z, p1i);
            const u64 nrr = sub2(z, rri);
            const u64 nqq = sub2(z, qqi);
            y1r = fma2(wax, p1r, y1r);  y1r = fma2(way, np1, y1r);
            y1i = fma2(wax, p1i, y1i);  y1i = fma2(way, p1r, y1i);
            yar = fma2(wbx, rrr, yar);  yar = fma2(wby, nrr, yar);
            yai = fma2(wbx, rri, yai);  yai = fma2(wby, rrr, yai);
            yar = fma2(wcx, qqr, yar);  yar = fma2(wcy, nqq, yar);
            yai = fma2(wcx, qqi, yai);  yai = fma2(wcy, qqr, yai);
        }
        // F += G[l-m]*y1 + E[l-m]*ya
        const u64 ngv = sub2(z, gv.y);
        const u64 nav = sub2(z, av.y);
        fr = fma2(gv.x, y1r, fr);  fr = fma2(ngv, y1i, fr);
        fi = fma2(gv.x, y1i, fi);  fi = fma2(gv.y, y1r, fi);
        fr = fma2(av.x, yar, fr);  fr = fma2(nav, yai, fr);
        fi = fma2(av.x, yai, fi);  fi = fma2(av.y, yar, fi);
        ++r;
    }

    if (ty > 0)
        sR[ty - 1][tx] = make_ulonglong2(fr, fi);
    __syncthreads();
    if (ty == 0) {
        #pragma unroll
        for (int j = 0; j < SPLIT - 1; ++j) {
            const ulonglong2 rr = sR[j][tx];
            fr = add2(fr, rr.x);  fi = add2(fi, rr.y);
        }
        const int l = base + tx;
        if (l >= NLW && l < SEQ - NLW) {
            const float Psf = exp10f(task[b * 4] * 0.1f) * 0.5f;
            const u64 g2 = pack2(0.01f * Psf);
            const u64 c01 = pack2(0.1f);
            const int gi = b * SEQ + l;
            const ulonglong2 ev = sE[li];
            u64 outr = fma2(g2, fr, fma2(c01, g_E1r[gi], ev.x));
            u64 outi = fma2(g2, fi, fma2(c01, g_E1i[gi], ev.y));
            const float2 orr = unpackf2(outr);
            const float2 oii = unpackf2(outi);
            out[b * OUTL + (l - NLW)] = make_float4(orr.x, oii.x, orr.y, oii.y);
        }
    }
}

extern "C" void kernel_launch(void* const* d_in, const int* in_sizes, int n_in,
                              void* d_out, int out_size)
{
    const float2* Er   = (const float2*)d_in[0];
    const float2* Ei   = (const float2*)d_in[1];
    const float*  task = (const float*)d_in[2];
    const float*  w1r  = (const float*)d_in[3];
    const float*  w1i  = (const float*)d_in[4];
    const float*  w2r  = (const float*)d_in[5];
    const float*  w2i  = (const float*)d_in[6];
    const float*  fcr  = (const float*)d_in[7];
    const float*  fci  = (const float*)d_in[8];

    dim3 grid(SEQ / TILE, BATCH);
    dim3 blk(TILE, SPLIT);
    stage1_kernel<<<grid, blk>>>(Er, Ei, task, w1r, w1i, w2r, w2i);
    stage2_kernel<<<grid, blk>>>(Er, Ei, task, fcr, fci, (float4*)d_out);
}